// round 8
// baseline (speedup 1.0000x reference)
#include <cuda_runtime.h>
#include <cuda_fp16.h>

#define N_PTS  262144
#define DIM    32
#define NQ     4
#define NK     256
#define TPB    512
#define NCHUNK (N_PTS / TPB)
#define GRID   148
#define ROWF   36                 // fp32 rows: 32 data + en@32 + pad; float4-aligned
#define ROWHB  80                 // half rows (-2e), ldmatrix-friendly
#define EPS    1.0f

#define OFF_HB   0
#define OFF_ENH  (NQ * NK * ROWHB)                 // 81920: half enorm table
#define OFF_CB   (OFF_ENH + NQ * NK * 2)           // 83968: fp32 rows (16B aligned)
#define SMEM_BYTES (OFF_CB + NQ * NK * ROWF * 4)   // 231424

__device__ double   g_block_loss[GRID];
__device__ unsigned g_done = 0;

__device__ __forceinline__ void mma16816(float& c0, float& c1, float& c2, float& c3,
                                         unsigned a0, unsigned a1, unsigned a2, unsigned a3,
                                         unsigned b0, unsigned b1)
{
    asm volatile("mma.sync.aligned.m16n8k16.row.col.f32.f16.f16.f32 "
                 "{%0,%1,%2,%3}, {%4,%5,%6,%7}, {%8,%9}, {%0,%1,%2,%3};"
                 : "+f"(c0), "+f"(c1), "+f"(c2), "+f"(c3)
                 : "r"(a0), "r"(a1), "r"(a2), "r"(a3), "r"(b0), "r"(b1));
}

__device__ __forceinline__ void ldmatrix_x4(unsigned& r0, unsigned& r1, unsigned& r2, unsigned& r3,
                                            unsigned saddr)
{
    asm volatile("ldmatrix.sync.aligned.m8n8.x4.shared.b16 {%0,%1,%2,%3}, [%4];"
                 : "=r"(r0), "=r"(r1), "=r"(r2), "=r"(r3) : "r"(saddr));
}

__device__ __forceinline__ unsigned sel4(unsigned v0, unsigned v1, unsigned v2, unsigned v3, int c)
{
    unsigned x = (c & 1) ? v1 : v0;
    unsigned y = (c & 1) ? v3 : v2;
    return (c & 2) ? y : x;
}

__device__ __forceinline__ unsigned h2bits(__half2 h) { return *reinterpret_cast<unsigned*>(&h); }
__device__ __forceinline__ __half2  bits2h(unsigned u) { return *reinterpret_cast<__half2*>(&u); }

__global__ void __launch_bounds__(TPB, 1)
rvq_main_kernel(const float* __restrict__ x,
                const float* __restrict__ codebooks,
                float* __restrict__ out)
{
    extern __shared__ __align__(16) char smraw[];
    __half*  s_hb   = (__half*)(smraw + OFF_HB);     // [1024][40] halfs (-2e), 80B rows
    __half*  s_enh  = (__half*)(smraw + OFF_ENH);    // [1024] half enorm
    __half2* s_enh2 = (__half2*)s_enh;
    float*   s_cb   = (float*)(smraw + OFF_CB);      // [1024][36] fp32 rows, en@slot32

    unsigned sbase;
    asm("{ .reg .u64 t; cvta.to.shared.u64 t, %1; cvt.u32.u64 %0, t; }"
        : "=r"(sbase) : "l"(smraw));

    const int tid  = threadIdx.x;
    const int lane = tid & 31;
    const int tg   = lane & 3;

    // --- stage: fp32 rows (+exact enorm in slot 32) ; half rows = -2e ; half enorm ---
    for (int c = tid; c < NQ * NK; c += TPB) {
        const float* g  = codebooks + (size_t)c * DIM;
        float*       d  = s_cb + (size_t)c * ROWF;
        __half*      ph = (__half*)((char*)s_hb + (size_t)c * ROWHB);
        float en = 0.f;
        #pragma unroll
        for (int i = 0; i < DIM; i++) {
            float v = g[i];
            d[i]  = v;
            ph[i] = __float2half_rn(-2.0f * v);
            en = __fadd_rn(en, __fmul_rn(v, v));
        }
        d[32]    = en;                       // exact enorm for verify
        s_enh[c] = __float2half_rn(en);      // approx enorm for scan
    }
    __syncthreads();

    const unsigned b_lanebase = sbase + OFF_HB
        + (unsigned)(lane & 7) * ROWHB + ((unsigned)(lane >> 3) << 4);

    const __half2 EPS2 = __float2half2_rn(EPS);
    const __half2 INF2 = __float2half2_rn(__int_as_float(0x7f800000));
    const float   INF  = __int_as_float(0x7f800000);

    double lsum = 0.0;

    for (int chunk = blockIdx.x; chunk < NCHUNK; chunk += GRID) {
        const int n = chunk * TPB + tid;

        float r[DIM], xq[DIM];
        {
            const float4* xr = (const float4*)(x + (size_t)n * DIM);
            #pragma unroll
            for (int j = 0; j < 8; j++) {
                float4 v = xr[j];
                r[4*j+0] = v.x; r[4*j+1] = v.y; r[4*j+2] = v.z; r[4*j+3] = v.w;
                xq[4*j+0] = 0.f; xq[4*j+1] = 0.f; xq[4*j+2] = 0.f; xq[4*j+3] = 0.f;
            }
        }

        float* oi = out + (size_t)N_PTS * DIM + 1 + (size_t)n * NQ;

        #pragma unroll 1
        for (int q = 0; q < NQ; q++) {
            // exact sequential rnorm (reference rounding)
            float rn = 0.f;
            #pragma unroll
            for (int i = 0; i < DIM; i++)
                rn = __fadd_rn(rn, __fmul_rn(r[i], r[i]));

            // ---- A fragments via shuffles (residual half2 words) ----
            unsigned h2u[16];
            #pragma unroll
            for (int w = 0; w < 16; w++) {
                __half2 hh = __floats2half2_rn(r[2*w], r[2*w+1]);
                h2u[w] = h2bits(hh);
            }
            unsigned A0[8], A1[8];
            #pragma unroll
            for (int mt = 0; mt < 2; mt++) {
                unsigned* A = mt ? A1 : A0;
                int src0 = mt * 16 + (lane >> 2);
                int src1 = src0 + 8;
                #pragma unroll
                for (int b4 = 0; b4 < 4; b4++) {
                    unsigned s00 = __shfl_sync(0xffffffffu, h2u[4*b4+0], src0);
                    unsigned s01 = __shfl_sync(0xffffffffu, h2u[4*b4+1], src0);
                    unsigned s02 = __shfl_sync(0xffffffffu, h2u[4*b4+2], src0);
                    unsigned s03 = __shfl_sync(0xffffffffu, h2u[4*b4+3], src0);
                    unsigned s10 = __shfl_sync(0xffffffffu, h2u[4*b4+0], src1);
                    unsigned s11 = __shfl_sync(0xffffffffu, h2u[4*b4+1], src1);
                    unsigned s12 = __shfl_sync(0xffffffffu, h2u[4*b4+2], src1);
                    unsigned s13 = __shfl_sync(0xffffffffu, h2u[4*b4+3], src1);
                    A[2*b4 + 0] = sel4(s00, s01, s02, s03, tg);
                    A[2*b4 + 1] = sel4(s10, s11, s12, s13, tg);
                }
            }

            const unsigned bq   = b_lanebase + (unsigned)q * NK * ROWHB;
            const __half2* enq2 = s_enh2 + q * (NK / 2);
            const float*   cq   = s_cb + (size_t)q * NK * ROWF;

            // ---- tensor-core scan; scores = (-2dot) + en in half2 ----
            __half2 thA0 = INF2, thB0 = INF2, thA1 = INF2, thB1 = INF2;
            unsigned long long flA0 = 0, flA1 = 0, flB0m0 = 0;  // (renamed below)
            unsigned long long f0w0 = 0, f0w1 = 0, f1w0 = 0, f1w1 = 0; // [mt][word]
            (void)flA0; (void)flA1; (void)flB0m0;

            #pragma unroll 4
            for (int t = 0; t < 32; t++) {
                unsigned b0, b1, b2, b3;
                ldmatrix_x4(b0, b1, b2, b3, bq + (unsigned)t * (8 * ROWHB));
                __half2 en2 = enq2[t * 4 + tg];

                // scores
                float c00=0.f,c01=0.f,c02=0.f,c03=0.f;
                mma16816(c00,c01,c02,c03, A0[0],A0[1],A0[2],A0[3], b0,b1);
                mma16816(c00,c01,c02,c03, A0[4],A0[5],A0[6],A0[7], b2,b3);
                float c10=0.f,c11=0.f,c12=0.f,c13=0.f;
                mma16816(c10,c11,c12,c13, A1[0],A1[1],A1[2],A1[3], b0,b1);
                mma16816(c10,c11,c12,c13, A1[4],A1[5],A1[6],A1[7], b2,b3);

                __half2 s0A = __hadd2(__floats2half2_rn(c00, c01), en2);
                __half2 s0B = __hadd2(__floats2half2_rn(c02, c03), en2);
                __half2 s1A = __hadd2(__floats2half2_rn(c10, c11), en2);
                __half2 s1B = __hadd2(__floats2half2_rn(c12, c13), en2);

                // running thresholds (min + EPS), per col-lane
                thA0 = __hmin2(thA0, __hadd2(s0A, EPS2));
                thB0 = __hmin2(thB0, __hadd2(s0B, EPS2));
                thA1 = __hmin2(thA1, __hadd2(s1A, EPS2));
                thB1 = __hmin2(thB1, __hadd2(s1B, EPS2));

                // quad-sync thresholds BEFORE flagging every 4 tiles (incl. t=0)
                if ((t & 3) == 0) {
                    unsigned u;
                    u = h2bits(thA0); u = h2bits(__hmin2(bits2h(u), bits2h(__shfl_xor_sync(0xffffffffu,u,1))));
                                      u = h2bits(__hmin2(bits2h(u), bits2h(__shfl_xor_sync(0xffffffffu,u,2)))); thA0 = bits2h(u);
                    u = h2bits(thB0); u = h2bits(__hmin2(bits2h(u), bits2h(__shfl_xor_sync(0xffffffffu,u,1))));
                                      u = h2bits(__hmin2(bits2h(u), bits2h(__shfl_xor_sync(0xffffffffu,u,2)))); thB0 = bits2h(u);
                    u = h2bits(thA1); u = h2bits(__hmin2(bits2h(u), bits2h(__shfl_xor_sync(0xffffffffu,u,1))));
                                      u = h2bits(__hmin2(bits2h(u), bits2h(__shfl_xor_sync(0xffffffffu,u,2)))); thA1 = bits2h(u);
                    u = h2bits(thB1); u = h2bits(__hmin2(bits2h(u), bits2h(__shfl_xor_sync(0xffffffffu,u,1))));
                                      u = h2bits(__hmin2(bits2h(u), bits2h(__shfl_xor_sync(0xffffffffu,u,2)))); thB1 = bits2h(u);
                }

                // flags: sign bits of (s - th)  -> 4-bit nibble [rA.c0, rA.c1, rB.c0, rB.c1]
                {
                    unsigned dA = h2bits(__hsub2(s0A, thA0));
                    unsigned dB = h2bits(__hsub2(s0B, thB0));
                    unsigned xm = __byte_perm(dA, dB, 0x7531);
                    unsigned nib = (((xm & 0x80808080u) >> 7) * 0x01020408u) >> 24;
                    unsigned long long n64 = (unsigned long long)nib << ((4*t) & 63);
                    if (t < 16) f0w0 |= n64; else f0w1 |= n64;
                }
                {
                    unsigned dA = h2bits(__hsub2(s1A, thA1));
                    unsigned dB = h2bits(__hsub2(s1B, thB1));
                    unsigned xm = __byte_perm(dA, dB, 0x7531);
                    unsigned nib = (((xm & 0x80808080u) >> 7) * 0x01020408u) >> 24;
                    unsigned long long n64 = (unsigned long long)nib << ((4*t) & 63);
                    if (t < 16) f1w0 |= n64; else f1w1 |= n64;
                }
            }

            // ---- gather flags to owner point, exact verify (reference rounding) ----
            const int rr      = lane & 15;
            const int mymt    = lane >> 4;
            const unsigned long long rowmask =
                (rr >= 8) ? 0xCCCCCCCCCCCCCCCCull : 0x3333333333333333ull;
            const int srcbase = (rr & 7) << 2;

            float best = INF;
            int   bi   = 0;
            #pragma unroll
            for (int j = 0; j < 4; j++) {
                int src = srcbase + j;
                unsigned long long w00 = __shfl_sync(0xffffffffu, f0w0, src);
                unsigned long long w01 = __shfl_sync(0xffffffffu, f0w1, src);
                unsigned long long w10 = __shfl_sync(0xffffffffu, f1w0, src);
                unsigned long long w11 = __shfl_sync(0xffffffffu, f1w1, src);
                unsigned long long wa = (mymt ? w10 : w00) & rowmask;
                unsigned long long wb = (mymt ? w11 : w01) & rowmask;

                while (wa) {
                    int b = __ffsll((long long)wa) - 1; wa &= wa - 1;
                    int k = ((b >> 2) << 3) + 2*j + (b & 1);
                    const float4* e4 = (const float4*)(cq + (size_t)k * ROWF);
                    float acc = 0.f;
                    #pragma unroll
                    for (int jj = 0; jj < 8; jj++) {
                        float4 v = e4[jj];
                        acc = fmaf(r[4*jj+0], v.x, acc);
                        acc = fmaf(r[4*jj+1], v.y, acc);
                        acc = fmaf(r[4*jj+2], v.z, acc);
                        acc = fmaf(r[4*jj+3], v.w, acc);
                    }
                    float s = __fadd_rn(rn, -2.0f * acc);
                    s = __fadd_rn(s, cq[(size_t)k * ROWF + 32]);
                    if (s < best || (s == best && k < bi)) { best = s; bi = k; }
                }
                while (wb) {
                    int b = __ffsll((long long)wb) - 1; wb &= wb - 1;
                    int k = ((16 + (b >> 2)) << 3) + 2*j + (b & 1);
                    const float4* e4 = (const float4*)(cq + (size_t)k * ROWF);
                    float acc = 0.f;
                    #pragma unroll
                    for (int jj = 0; jj < 8; jj++) {
                        float4 v = e4[jj];
                        acc = fmaf(r[4*jj+0], v.x, acc);
                        acc = fmaf(r[4*jj+1], v.y, acc);
                        acc = fmaf(r[4*jj+2], v.z, acc);
                        acc = fmaf(r[4*jj+3], v.w, acc);
                    }
                    float s = __fadd_rn(rn, -2.0f * acc);
                    s = __fadd_rn(s, cq[(size_t)k * ROWF + 32]);
                    if (s < best || (s == best && k < bi)) { best = s; bi = k; }
                }
            }

            oi[q] = (float)bi;

            // ---- exact scan-carry: c=fl(q-r); x_res=fl(r+c); xq+=x_res; r-=x_res ----
            const float4* eb4 = (const float4*)(cq + (size_t)bi * ROWF);
            float lq = 0.f;
            #pragma unroll
            for (int jj = 0; jj < 8; jj++) {
                float4 v = eb4[jj];
                float qv[4] = {v.x, v.y, v.z, v.w};
                #pragma unroll
                for (int u = 0; u < 4; u++) {
                    int i = 4*jj + u;
                    float c   = __fadd_rn(qv[u], -r[i]);
                    float xr_ = __fadd_rn(r[i], c);
                    xq[i]     = __fadd_rn(xq[i], xr_);
                    r[i]      = __fadd_rn(r[i], -xr_);
                    lq       += __fmul_rn(c, c);
                }
            }
            lsum += (double)lq;
        }

        // write x_q
        {
            float4* o = (float4*)(out + (size_t)n * DIM);
            #pragma unroll
            for (int j = 0; j < 8; j++) {
                float4 v;
                v.x = xq[4*j+0]; v.y = xq[4*j+1]; v.z = xq[4*j+2]; v.w = xq[4*j+3];
                o[j] = v;
            }
        }
    }

    // ---- deterministic per-CTA loss reduction ----
    #pragma unroll
    for (int o = 16; o > 0; o >>= 1)
        lsum += __shfl_down_sync(0xffffffffu, lsum, o);

    __shared__ double wsum[TPB / 32];
    if ((tid & 31) == 0) wsum[tid >> 5] = lsum;
    __syncthreads();
    if (tid == 0) {
        double s = 0.0;
        #pragma unroll
        for (int w = 0; w < TPB / 32; w++) s += wsum[w];
        g_block_loss[blockIdx.x] = s;
    }

    // ---- fused finalize: last CTA reduces block sums ----
    __threadfence();
    __shared__ int s_last;
    if (tid == 0) {
        unsigned o = atomicAdd(&g_done, 1u);
        s_last = (o == GRID - 1);
    }
    __syncthreads();
    if (s_last) {
        double v = (tid < GRID) ? g_block_loss[tid] : 0.0;
        #pragma unroll
        for (int o = 16; o > 0; o >>= 1)
            v += __shfl_down_sync(0xffffffffu, v, o);
        if ((tid & 31) == 0) wsum[tid >> 5] = v;
        __syncthreads();
        if (tid == 0) {
            double s = 0.0;
            #pragma unroll
            for (int w = 0; w < TPB / 32; w++) s += wsum[w];
            out[(size_t)N_PTS * DIM] =
                (float)(1.25 * s / ((double)NQ * (double)N_PTS * (double)DIM));
            g_done = 0;   // reset for next graph replay
        }
    }
}

extern "C" void kernel_launch(void* const* d_in, const int* in_sizes, int n_in,
                              void* d_out, int out_size)
{
    const float* x   = (const float*)d_in[0];
    const float* cb  = (const float*)d_in[1];
    float*       out = (float*)d_out;

    cudaFuncSetAttribute(rvq_main_kernel,
                         cudaFuncAttributeMaxDynamicSharedMemorySize, SMEM_BYTES);

    rvq_main_kernel<<<GRID, TPB, SMEM_BYTES>>>(x, cb, out);
}

// round 9
// speedup vs baseline: 1.0705x; 1.0705x over previous
#include <cuda_runtime.h>
#include <cuda_fp16.h>

#define N_PTS  262144
#define DIM    32
#define NQ     4
#define NK     256
#define TPB    512
#define NCHUNK (N_PTS / TPB)
#define GRID   148
#define ROWF   33                 // fp32 verify rows, conflict-free scalar gather
#define ROWHB  64                 // half rows (-2e), conflict-free ldmatrix
#define ROWA   80                 // A-stage rows, conflict-free STS.128 + ldmatrix
#define EPS    0.75f

#define OFF_HB   0                                   // 1024*64   = 65536
#define OFF_EN   (NQ * NK * ROWHB)                   // 65536 (fp32 enorm, 4096)
#define OFF_CB   (OFF_EN + NQ * NK * 4)              // 69632 (fp32 rows, 135168)
#define OFF_AST  (OFF_CB + NQ * NK * ROWF * 4)       // 204800 (16 warps * 1280)
#define SMEM_BYTES (OFF_AST + 16 * 16 * ROWA)        // 225280

__device__ double   g_block_loss[GRID];
__device__ unsigned g_done = 0;

__device__ __forceinline__ void mma16816(float& c0, float& c1, float& c2, float& c3,
                                         unsigned a0, unsigned a1, unsigned a2, unsigned a3,
                                         unsigned b0, unsigned b1)
{
    asm volatile("mma.sync.aligned.m16n8k16.row.col.f32.f16.f16.f32 "
                 "{%0,%1,%2,%3}, {%4,%5,%6,%7}, {%8,%9}, {%0,%1,%2,%3};"
                 : "+f"(c0), "+f"(c1), "+f"(c2), "+f"(c3)
                 : "r"(a0), "r"(a1), "r"(a2), "r"(a3), "r"(b0), "r"(b1));
}

__device__ __forceinline__ void ldmatrix_x4(unsigned& r0, unsigned& r1, unsigned& r2, unsigned& r3,
                                            unsigned saddr)
{
    asm volatile("ldmatrix.sync.aligned.m8n8.x4.shared.b16 {%0,%1,%2,%3}, [%4];"
                 : "=r"(r0), "=r"(r1), "=r"(r2), "=r"(r3) : "r"(saddr));
}

__device__ __forceinline__ void sts128(unsigned addr, unsigned v0, unsigned v1,
                                       unsigned v2, unsigned v3)
{
    asm volatile("st.shared.v4.b32 [%0], {%1,%2,%3,%4};"
                 :: "r"(addr), "r"(v0), "r"(v1), "r"(v2), "r"(v3));
}

__global__ void __launch_bounds__(TPB, 1)
rvq_main_kernel(const float* __restrict__ x,
                const float* __restrict__ codebooks,
                float* __restrict__ out)
{
    extern __shared__ __align__(16) char smraw[];
    __half* s_hb = (__half*)(smraw + OFF_HB);    // [1024][32] halfs of -2e, 64B rows
    float*  s_en = (float*)(smraw + OFF_EN);     // [1024] exact fp32 enorm
    float*  s_cb = (float*)(smraw + OFF_CB);     // [1024][33] fp32 rows

    unsigned sbase;
    asm("{ .reg .u64 t; cvta.to.shared.u64 t, %1; cvt.u32.u64 %0, t; }"
        : "=r"(sbase) : "l"(smraw));

    const int tid  = threadIdx.x;
    const int lane = tid & 31;
    const int tg   = lane & 3;

    // --- stage: fp32 rows + exact sequential enorm ; half rows = -2e ---
    for (int c = tid; c < NQ * NK; c += TPB) {
        const float* g  = codebooks + (size_t)c * DIM;
        float*       d  = s_cb + (size_t)c * ROWF;
        __half*      ph = (__half*)((char*)s_hb + (size_t)c * ROWHB);
        float en = 0.f;
        #pragma unroll
        for (int i = 0; i < DIM; i++) {
            float v = g[i];
            d[i]  = v;
            ph[i] = __float2half_rn(-2.0f * v);
            en = __fadd_rn(en, __fmul_rn(v, v));
        }
        s_en[c] = en;
    }
    __syncthreads();

    const unsigned b_lanebase = sbase + OFF_HB
        + (unsigned)(lane & 7) * ROWHB + ((unsigned)(lane >> 3) << 4);
    const unsigned astage = sbase + OFF_AST + (unsigned)(tid >> 5) * (16 * ROWA);
    const unsigned a_st   = astage + (unsigned)(lane & 15) * ROWA;
    const unsigned a_ld   = astage + (unsigned)(lane & 15) * ROWA + ((unsigned)(lane >> 4) << 4);

    const float INF = __int_as_float(0x7f800000);
    double lsum = 0.0;

    for (int chunk = blockIdx.x; chunk < NCHUNK; chunk += GRID) {
        const int n = chunk * TPB + tid;

        float r[DIM], xq[DIM];
        {
            const float4* xr = (const float4*)(x + (size_t)n * DIM);
            #pragma unroll
            for (int j = 0; j < 8; j++) {
                float4 v = xr[j];
                r[4*j+0] = v.x; r[4*j+1] = v.y; r[4*j+2] = v.z; r[4*j+3] = v.w;
                xq[4*j+0] = 0.f; xq[4*j+1] = 0.f; xq[4*j+2] = 0.f; xq[4*j+3] = 0.f;
            }
        }

        float* oi = out + (size_t)N_PTS * DIM + 1 + (size_t)n * NQ;

        #pragma unroll 1
        for (int q = 0; q < NQ; q++) {
            // exact sequential rnorm (reference rounding)
            float rn = 0.f;
            #pragma unroll
            for (int i = 0; i < DIM; i++)
                rn = __fadd_rn(rn, __fmul_rn(r[i], r[i]));

            // ---- residual -> half2 words ----
            unsigned h2u[16];
            #pragma unroll
            for (int w = 0; w < 16; w++) {
                __half2 hh = __floats2half2_rn(r[2*w], r[2*w+1]);
                h2u[w] = *(unsigned*)&hh;
            }

            // ---- A fragments via per-warp smem stage + ldmatrix ----
            unsigned A0[8], A1[8];
            #pragma unroll
            for (int mt = 0; mt < 2; mt++) {
                if ((lane >> 4) == mt) {
                    sts128(a_st,      h2u[0],  h2u[1],  h2u[2],  h2u[3]);
                    sts128(a_st + 16, h2u[4],  h2u[5],  h2u[6],  h2u[7]);
                    sts128(a_st + 32, h2u[8],  h2u[9],  h2u[10], h2u[11]);
                    sts128(a_st + 48, h2u[12], h2u[13], h2u[14], h2u[15]);
                }
                __syncwarp();
                unsigned* A = mt ? A1 : A0;
                ldmatrix_x4(A[0], A[1], A[2], A[3], a_ld);        // k0-15
                ldmatrix_x4(A[4], A[5], A[6], A[7], a_ld + 32);   // k16-31
                __syncwarp();
            }

            const unsigned bq  = b_lanebase + (unsigned)q * NK * ROWHB;
            const float*   enq = s_en + q * NK;
            const float*   cq  = s_cb + (size_t)q * NK * ROWF;

            // ---- tensor-core scan: score = en - 2*dot via C-init = en, B = -2e ----
            unsigned long long f0w0 = 0, f0w1 = 0, f1w0 = 0, f1w1 = 0;
            float th00 = INF, th01 = INF, th10 = INF, th11 = INF;

            #pragma unroll 4
            for (int t = 0; t < 32; t++) {
                unsigned b0, b1, b2, b3;
                ldmatrix_x4(b0, b1, b2, b3, bq + (unsigned)t * (8 * ROWHB));
                float2 en2 = *(const float2*)(enq + t * 8 + 2 * tg);

                // mt = 0
                {
                    float s0 = en2.x, s1 = en2.y, s2 = en2.x, s3 = en2.y;
                    mma16816(s0, s1, s2, s3, A0[0], A0[1], A0[2], A0[3], b0, b1);
                    mma16816(s0, s1, s2, s3, A0[4], A0[5], A0[6], A0[7], b2, b3);
                    th00 = fminf(th00, fminf(s0, s1) + EPS);
                    th01 = fminf(th01, fminf(s2, s3) + EPS);
                    unsigned long long bits =
                          ((unsigned long long)(s0 <= th00))
                        | ((unsigned long long)(s1 <= th00) << 1);
                    unsigned long long bits2 =
                          ((unsigned long long)(s2 <= th01))
                        | ((unsigned long long)(s3 <= th01) << 1);
                    f0w0 |= bits  << (2*t);
                    f0w1 |= bits2 << (2*t);
                }
                // mt = 1
                {
                    float s0 = en2.x, s1 = en2.y, s2 = en2.x, s3 = en2.y;
                    mma16816(s0, s1, s2, s3, A1[0], A1[1], A1[2], A1[3], b0, b1);
                    mma16816(s0, s1, s2, s3, A1[4], A1[5], A1[6], A1[7], b2, b3);
                    th10 = fminf(th10, fminf(s0, s1) + EPS);
                    th11 = fminf(th11, fminf(s2, s3) + EPS);
                    unsigned long long bits =
                          ((unsigned long long)(s0 <= th10))
                        | ((unsigned long long)(s1 <= th10) << 1);
                    unsigned long long bits2 =
                          ((unsigned long long)(s2 <= th11))
                        | ((unsigned long long)(s3 <= th11) << 1);
                    f1w0 |= bits  << (2*t);
                    f1w1 |= bits2 << (2*t);
                }
                // quad-sync thresholds every 8 tiles (superset-safe tightening)
                if ((t & 7) == 3) {
                    th00 = fminf(th00, __shfl_xor_sync(0xffffffffu, th00, 1));
                    th00 = fminf(th00, __shfl_xor_sync(0xffffffffu, th00, 2));
                    th01 = fminf(th01, __shfl_xor_sync(0xffffffffu, th01, 1));
                    th01 = fminf(th01, __shfl_xor_sync(0xffffffffu, th01, 2));
                    th10 = fminf(th10, __shfl_xor_sync(0xffffffffu, th10, 1));
                    th10 = fminf(th10, __shfl_xor_sync(0xffffffffu, th10, 2));
                    th11 = fminf(th11, __shfl_xor_sync(0xffffffffu, th11, 1));
                    th11 = fminf(th11, __shfl_xor_sync(0xffffffffu, th11, 2));
                }
            }

            // ---- gather flags to owning point ----
            // point = lane; mt = lane>>4; rr = lane&15; rowhalf = rr>=8 -> f?w1
            const int rr      = lane & 15;
            const int mycombo = ((lane >> 4) << 1) | (rr >= 8 ? 1 : 0);
            const int srcbase = (rr & 7) << 2;
            unsigned long long gw[4];
            #pragma unroll
            for (int j = 0; j < 4; j++) {
                int src = srcbase + j;
                unsigned long long t0 = __shfl_sync(0xffffffffu, f0w0, src);
                unsigned long long t1 = __shfl_sync(0xffffffffu, f0w1, src);
                unsigned long long t2 = __shfl_sync(0xffffffffu, f1w0, src);
                unsigned long long t3 = __shfl_sync(0xffffffffu, f1w1, src);
                gw[j] = (mycombo == 0) ? t0 : (mycombo == 1) ? t1
                      : (mycombo == 2) ? t2 : t3;
            }

            // ---- exact verification (reference rounding); tie-break: smaller k ----
            float best = INF;
            int   bi   = 0;
            #pragma unroll
            for (int j = 0; j < 4; j++) {
                unsigned long long msk = gw[j];
                while (msk) {
                    int b = __ffsll((long long)msk) - 1;
                    msk &= msk - 1;
                    int k = ((b >> 1) << 3) + 2 * j + (b & 1);
                    const float* e = cq + (size_t)k * ROWF;
                    float acc = 0.f;
                    #pragma unroll
                    for (int i = 0; i < DIM; i++)
                        acc = fmaf(r[i], e[i], acc);
                    float s = __fadd_rn(rn, -2.0f * acc);
                    s = __fadd_rn(s, enq[k]);
                    if (s < best || (s == best && k < bi)) { best = s; bi = k; }
                }
            }

            oi[q] = (float)bi;

            // ---- exact scan-carry: c=fl(q-r); x_res=fl(r+c); xq+=x_res; r-=x_res ----
            const float* eb = cq + (size_t)bi * ROWF;
            float lq = 0.f;
            #pragma unroll
            for (int i = 0; i < DIM; i++) {
                float qi  = eb[i];
                float c   = __fadd_rn(qi, -r[i]);
                float xr_ = __fadd_rn(r[i], c);
                xq[i]     = __fadd_rn(xq[i], xr_);
                r[i]      = __fadd_rn(r[i], -xr_);
                lq       += __fmul_rn(c, c);
            }
            lsum += (double)lq;
        }

        // write x_q
        {
            float4* o = (float4*)(out + (size_t)n * DIM);
            #pragma unroll
            for (int j = 0; j < 8; j++) {
                float4 v;
                v.x = xq[4*j+0]; v.y = xq[4*j+1]; v.z = xq[4*j+2]; v.w = xq[4*j+3];
                o[j] = v;
            }
        }
    }

    // ---- deterministic per-CTA loss reduction ----
    #pragma unroll
    for (int o = 16; o > 0; o >>= 1)
        lsum += __shfl_down_sync(0xffffffffu, lsum, o);

    __shared__ double wsum[TPB / 32];
    if ((tid & 31) == 0) wsum[tid >> 5] = lsum;
    __syncthreads();
    if (tid == 0) {
        double s = 0.0;
        #pragma unroll
        for (int w = 0; w < TPB / 32; w++) s += wsum[w];
        g_block_loss[blockIdx.x] = s;
    }

    // ---- fused finalize: last CTA reduces block sums ----
    __threadfence();
    __shared__ int s_last;
    if (tid == 0) {
        unsigned o = atomicAdd(&g_done, 1u);
        s_last = (o == GRID - 1);
    }
    __syncthreads();
    if (s_last) {
        double v = (tid < GRID) ? g_block_loss[tid] : 0.0;
        #pragma unroll
        for (int o = 16; o > 0; o >>= 1)
            v += __shfl_down_sync(0xffffffffu, v, o);
        if ((tid & 31) == 0) wsum[tid >> 5] = v;
        __syncthreads();
        if (tid == 0) {
            double s = 0.0;
            #pragma unroll
            for (int w = 0; w < TPB / 32; w++) s += wsum[w];
            out[(size_t)N_PTS * DIM] =
                (float)(1.25 * s / ((double)NQ * (double)N_PTS * (double)DIM));
            g_done = 0;   // reset for next graph replay
        }
    }
}

extern "C" void kernel_launch(void* const* d_in, const int* in_sizes, int n_in,
                              void* d_out, int out_size)
{
    const float* x   = (const float*)d_in[0];
    const float* cb  = (const float*)d_in[1];
    float*       out = (float*)d_out;

    cudaFuncSetAttribute(rvq_main_kernel,
                         cudaFuncAttributeMaxDynamicSharedMemorySize, SMEM_BYTES);

    rvq_main_kernel<<<GRID, TPB, SMEM_BYTES>>>(x, cb, out);
}

// round 10
// speedup vs baseline: 1.2600x; 1.1770x over previous
#include <cuda_runtime.h>
#include <cuda_fp16.h>

#define N_PTS  262144
#define DIM    32
#define NQ     4
#define NK     256
#define TPB    512
#define NCHUNK (N_PTS / TPB)
#define GRID   148
#define ROWF   36                 // fp32 rows: 32 data + en@32 + pad (float4 loads)
#define ROWHB  80                 // half rows (-2e): granules r*5 mod 8 distinct -> conflict-free ldmatrix
#define EPS    0.25f

#define OFF_HB   0                                   // 1024*80 = 81920
#define OFF_ENH  (NQ * NK * ROWHB)                   // 81920: half enorm (2048)
#define OFF_CB   (OFF_ENH + NQ * NK * 2)             // 83968: fp32 rows (147456)
#define SMEM_BYTES (OFF_CB + NQ * NK * ROWF * 4)     // 231424

__device__ double   g_block_loss[GRID];
__device__ unsigned g_done = 0;

__device__ __forceinline__ void mma16816(float& c0, float& c1, float& c2, float& c3,
                                         unsigned a0, unsigned a1, unsigned a2, unsigned a3,
                                         unsigned b0, unsigned b1)
{
    asm volatile("mma.sync.aligned.m16n8k16.row.col.f32.f16.f16.f32 "
                 "{%0,%1,%2,%3}, {%4,%5,%6,%7}, {%8,%9}, {%0,%1,%2,%3};"
                 : "+f"(c0), "+f"(c1), "+f"(c2), "+f"(c3)
                 : "r"(a0), "r"(a1), "r"(a2), "r"(a3), "r"(b0), "r"(b1));
}

__device__ __forceinline__ void ldmatrix_x4(unsigned& r0, unsigned& r1, unsigned& r2, unsigned& r3,
                                            unsigned saddr)
{
    asm volatile("ldmatrix.sync.aligned.m8n8.x4.shared.b16 {%0,%1,%2,%3}, [%4];"
                 : "=r"(r0), "=r"(r1), "=r"(r2), "=r"(r3) : "r"(saddr));
}

__device__ __forceinline__ unsigned sel4(unsigned v0, unsigned v1, unsigned v2, unsigned v3, int c)
{
    unsigned x = (c & 1) ? v1 : v0;
    unsigned y = (c & 1) ? v3 : v2;
    return (c & 2) ? y : x;
}

__global__ void __launch_bounds__(TPB, 1)
rvq_main_kernel(const float* __restrict__ x,
                const float* __restrict__ codebooks,
                float* __restrict__ out)
{
    extern __shared__ __align__(16) char smraw[];
    __half*  s_hb   = (__half*)(smraw + OFF_HB);     // [1024] rows of -2e, 80B stride
    __half2* s_enh2 = (__half2*)(smraw + OFF_ENH);   // [512] half2 enorm pairs
    float*   s_cb   = (float*)(smraw + OFF_CB);      // [1024][36] fp32 rows, en@32

    unsigned sbase;
    asm("{ .reg .u64 t; cvta.to.shared.u64 t, %1; cvt.u32.u64 %0, t; }"
        : "=r"(sbase) : "l"(smraw));

    const int tid  = threadIdx.x;
    const int lane = tid & 31;
    const int tg   = lane & 3;

    // --- stage: fp32 rows (+exact enorm @32) ; half rows = -2e ; half enorm ---
    for (int c = tid; c < NQ * NK; c += TPB) {
        const float* g  = codebooks + (size_t)c * DIM;
        float*       d  = s_cb + (size_t)c * ROWF;
        __half*      ph = (__half*)((char*)s_hb + (size_t)c * ROWHB);
        float en = 0.f;
        #pragma unroll
        for (int i = 0; i < DIM; i++) {
            float v = g[i];
            d[i]  = v;
            ph[i] = __float2half_rn(-2.0f * v);
            en = __fadd_rn(en, __fmul_rn(v, v));
        }
        d[32] = en;                                   // exact enorm (verify)
        ((__half*)s_enh2)[c] = __float2half_rn(en);   // approx enorm (scan)
    }
    __syncthreads();

    const unsigned b_lanebase = sbase + OFF_HB
        + (unsigned)(lane & 7) * ROWHB + ((unsigned)(lane >> 3) << 4);

    const float INF = __int_as_float(0x7f800000);
    double lsum = 0.0;

    for (int chunk = blockIdx.x; chunk < NCHUNK; chunk += GRID) {
        const int n = chunk * TPB + tid;

        float r[DIM], xq[DIM];
        {
            const float4* xr = (const float4*)(x + (size_t)n * DIM);
            #pragma unroll
            for (int j = 0; j < 8; j++) {
                float4 v = xr[j];
                r[4*j+0] = v.x; r[4*j+1] = v.y; r[4*j+2] = v.z; r[4*j+3] = v.w;
                xq[4*j+0] = 0.f; xq[4*j+1] = 0.f; xq[4*j+2] = 0.f; xq[4*j+3] = 0.f;
            }
        }

        float* oi = out + (size_t)N_PTS * DIM + 1 + (size_t)n * NQ;

        #pragma unroll 1
        for (int q = 0; q < NQ; q++) {
            // exact sequential rnorm (reference rounding)
            float rn = 0.f;
            #pragma unroll
            for (int i = 0; i < DIM; i++)
                rn = __fadd_rn(rn, __fmul_rn(r[i], r[i]));

            // ---- A fragments via shuffles (R6-validated mapping) ----
            unsigned h2u[16];
            #pragma unroll
            for (int w = 0; w < 16; w++) {
                __half2 hh = __floats2half2_rn(r[2*w], r[2*w+1]);
                h2u[w] = *(unsigned*)&hh;
            }
            unsigned A0[8], A1[8];
            #pragma unroll
            for (int mt = 0; mt < 2; mt++) {
                unsigned* A = mt ? A1 : A0;
                int src0 = mt * 16 + (lane >> 2);
                int src1 = src0 + 8;
                #pragma unroll
                for (int b4 = 0; b4 < 4; b4++) {
                    unsigned s00 = __shfl_sync(0xffffffffu, h2u[4*b4+0], src0);
                    unsigned s01 = __shfl_sync(0xffffffffu, h2u[4*b4+1], src0);
                    unsigned s02 = __shfl_sync(0xffffffffu, h2u[4*b4+2], src0);
                    unsigned s03 = __shfl_sync(0xffffffffu, h2u[4*b4+3], src0);
                    unsigned s10 = __shfl_sync(0xffffffffu, h2u[4*b4+0], src1);
                    unsigned s11 = __shfl_sync(0xffffffffu, h2u[4*b4+1], src1);
                    unsigned s12 = __shfl_sync(0xffffffffu, h2u[4*b4+2], src1);
                    unsigned s13 = __shfl_sync(0xffffffffu, h2u[4*b4+3], src1);
                    A[2*b4 + 0] = sel4(s00, s01, s02, s03, tg);
                    A[2*b4 + 1] = sel4(s10, s11, s12, s13, tg);
                }
            }

            const unsigned bq    = b_lanebase + (unsigned)q * NK * ROWHB;
            const __half2* enq2  = s_enh2 + q * (NK / 2);
            const float*   cq    = s_cb + (size_t)q * NK * ROWF;

            // ---- tensor-core scan: score = en - 2*dot (C-init = en, B = -2e) ----
            unsigned long long f00 = 0, f01 = 0, f10 = 0, f11 = 0;
            float th00 = INF, th01 = INF, th10 = INF, th11 = INF;

            #pragma unroll
            for (int t = 0; t < 32; t++) {
                unsigned b0, b1, b2, b3;
                ldmatrix_x4(b0, b1, b2, b3, bq + (unsigned)t * (8 * ROWHB));
                float2 en2 = __half22float2(enq2[t * 4 + tg]);

                // mt = 0 (points 0-15)
                {
                    float s0 = en2.x, s1 = en2.y, s2 = en2.x, s3 = en2.y;
                    mma16816(s0, s1, s2, s3, A0[0], A0[1], A0[2], A0[3], b0, b1);
                    mma16816(s0, s1, s2, s3, A0[4], A0[5], A0[6], A0[7], b2, b3);
                    th00 = fminf(th00, fminf(s0, s1) + EPS);
                    th01 = fminf(th01, fminf(s2, s3) + EPS);
                    f00 |= (((unsigned long long)(s0 <= th00))
                          | ((unsigned long long)(s1 <= th00) << 1)) << (2*t);
                    f01 |= (((unsigned long long)(s2 <= th01))
                          | ((unsigned long long)(s3 <= th01) << 1)) << (2*t);
                }
                // mt = 1 (points 16-31)
                {
                    float s0 = en2.x, s1 = en2.y, s2 = en2.x, s3 = en2.y;
                    mma16816(s0, s1, s2, s3, A1[0], A1[1], A1[2], A1[3], b0, b1);
                    mma16816(s0, s1, s2, s3, A1[4], A1[5], A1[6], A1[7], b2, b3);
                    th10 = fminf(th10, fminf(s0, s1) + EPS);
                    th11 = fminf(th11, fminf(s2, s3) + EPS);
                    f10 |= (((unsigned long long)(s0 <= th10))
                          | ((unsigned long long)(s1 <= th10) << 1)) << (2*t);
                    f11 |= (((unsigned long long)(s2 <= th11))
                          | ((unsigned long long)(s3 <= th11) << 1)) << (2*t);
                }
                // quad-sync thresholds every 4 tiles (superset-safe tightening)
                if ((t & 3) == 3) {
                    th00 = fminf(th00, __shfl_xor_sync(0xffffffffu, th00, 1));
                    th00 = fminf(th00, __shfl_xor_sync(0xffffffffu, th00, 2));
                    th01 = fminf(th01, __shfl_xor_sync(0xffffffffu, th01, 1));
                    th01 = fminf(th01, __shfl_xor_sync(0xffffffffu, th01, 2));
                    th10 = fminf(th10, __shfl_xor_sync(0xffffffffu, th10, 1));
                    th10 = fminf(th10, __shfl_xor_sync(0xffffffffu, th10, 2));
                    th11 = fminf(th11, __shfl_xor_sync(0xffffffffu, th11, 1));
                    th11 = fminf(th11, __shfl_xor_sync(0xffffffffu, th11, 2));
                }
            }

            // ---- gather flags to owning point (R6-validated) ----
            const int rr      = lane & 15;
            const int mycombo = ((lane >> 4) << 1) | (rr >= 8 ? 1 : 0);
            const int srcbase = (rr & 7) << 2;
            unsigned long long gw[4];
            #pragma unroll
            for (int j = 0; j < 4; j++) {
                int src = srcbase + j;
                unsigned long long t0 = __shfl_sync(0xffffffffu, f00, src);
                unsigned long long t1 = __shfl_sync(0xffffffffu, f01, src);
                unsigned long long t2 = __shfl_sync(0xffffffffu, f10, src);
                unsigned long long t3 = __shfl_sync(0xffffffffu, f11, src);
                gw[j] = (mycombo == 0) ? t0 : (mycombo == 1) ? t1
                      : (mycombo == 2) ? t2 : t3;
            }

            // ---- exact verification (reference rounding); tie-break: smaller k ----
            float best = INF;
            int   bi   = 0;
            #pragma unroll
            for (int j = 0; j < 4; j++) {
                unsigned long long msk = gw[j];
                while (msk) {
                    int b = __ffsll((long long)msk) - 1;
                    msk &= msk - 1;
                    int k = ((b >> 1) << 3) + 2 * j + (b & 1);
                    const float4* e4 = (const float4*)(cq + (size_t)k * ROWF);
                    float acc = 0.f;
                    #pragma unroll
                    for (int jj = 0; jj < 8; jj++) {
                        float4 v = e4[jj];
                        acc = fmaf(r[4*jj+0], v.x, acc);
                        acc = fmaf(r[4*jj+1], v.y, acc);
                        acc = fmaf(r[4*jj+2], v.z, acc);
                        acc = fmaf(r[4*jj+3], v.w, acc);
                    }
                    float s = __fadd_rn(rn, -2.0f * acc);
                    s = __fadd_rn(s, cq[(size_t)k * ROWF + 32]);
                    if (s < best || (s == best && k < bi)) { best = s; bi = k; }
                }
            }

            oi[q] = (float)bi;

            // ---- exact scan-carry: c=fl(q-r); x_res=fl(r+c); xq+=x_res; r-=x_res ----
            const float4* eb4 = (const float4*)(cq + (size_t)bi * ROWF);
            float lq = 0.f;
            #pragma unroll
            for (int jj = 0; jj < 8; jj++) {
                float4 v = eb4[jj];
                float qv[4] = {v.x, v.y, v.z, v.w};
                #pragma unroll
                for (int u = 0; u < 4; u++) {
                    int i = 4*jj + u;
                    float c   = __fadd_rn(qv[u], -r[i]);
                    float xr_ = __fadd_rn(r[i], c);
                    xq[i]     = __fadd_rn(xq[i], xr_);
                    r[i]      = __fadd_rn(r[i], -xr_);
                    lq       += __fmul_rn(c, c);
                }
            }
            lsum += (double)lq;
        }

        // write x_q
        {
            float4* o = (float4*)(out + (size_t)n * DIM);
            #pragma unroll
            for (int j = 0; j < 8; j++) {
                float4 v;
                v.x = xq[4*j+0]; v.y = xq[4*j+1]; v.z = xq[4*j+2]; v.w = xq[4*j+3];
                o[j] = v;
            }
        }
    }

    // ---- deterministic per-CTA loss reduction ----
    #pragma unroll
    for (int o = 16; o > 0; o >>= 1)
        lsum += __shfl_down_sync(0xffffffffu, lsum, o);

    __shared__ double wsum[TPB / 32];
    if ((tid & 31) == 0) wsum[tid >> 5] = lsum;
    __syncthreads();
    if (tid == 0) {
        double s = 0.0;
        #pragma unroll
        for (int w = 0; w < TPB / 32; w++) s += wsum[w];
        g_block_loss[blockIdx.x] = s;
    }

    // ---- fused finalize: last CTA reduces block sums ----
    __threadfence();
    __shared__ int s_last;
    if (tid == 0) {
        unsigned o = atomicAdd(&g_done, 1u);
        s_last = (o == GRID - 1);
    }
    __syncthreads();
    if (s_last) {
        double v = (tid < GRID) ? g_block_loss[tid] : 0.0;
        #pragma unroll
        for (int o = 16; o > 0; o >>= 1)
            v += __shfl_down_sync(0xffffffffu, v, o);
        if ((tid & 31) == 0) wsum[tid >> 5] = v;
        __syncthreads();
        if (tid == 0) {
            double s = 0.0;
            #pragma unroll
            for (int w = 0; w < TPB / 32; w++) s += wsum[w];
            out[(size_t)N_PTS * DIM] =
                (float)(1.25 * s / ((double)NQ * (double)N_PTS * (double)DIM));
            g_done = 0;   // reset for next graph replay
        }
    }
}

extern "C" void kernel_launch(void* const* d_in, const int* in_sizes, int n_in,
                              void* d_out, int out_size)
{
    const float* x   = (const float*)d_in[0];
    const float* cb  = (const float*)d_in[1];
    float*       out = (float*)d_out;

    cudaFuncSetAttribute(rvq_main_kernel,
                         cudaFuncAttributeMaxDynamicSharedMemorySize, SMEM_BYTES);

    rvq_main_kernel<<<GRID, TPB, SMEM_BYTES>>>(x, cb, out);
}

// round 11
// speedup vs baseline: 1.2639x; 1.0030x over previous
#include <cuda_runtime.h>
#include <cuda_fp16.h>

#define N_PTS  262144
#define DIM    32
#define NQ     4
#define NK     256
#define TPB    512
#define NCHUNK (N_PTS / TPB)
#define GRID   148
#define ROWF   36                 // fp32 rows: 32 data + en@32 + pad (float4 loads)
#define ROWHB  80                 // half rows (-2e): conflict-free ldmatrix
#define EPS    0.25f

#define OFF_HB   0                                   // 1024*80 = 81920
#define OFF_ENH  (NQ * NK * ROWHB)                   // 81920: half enorm (2048)
#define OFF_CB   (OFF_ENH + NQ * NK * 2)             // 83968: fp32 rows (147456)
#define SMEM_BYTES (OFF_CB + NQ * NK * ROWF * 4)     // 231424

__device__ double   g_block_loss[GRID];
__device__ unsigned g_done = 0;

__device__ __forceinline__ void mma16816(float& c0, float& c1, float& c2, float& c3,
                                         unsigned a0, unsigned a1, unsigned a2, unsigned a3,
                                         unsigned b0, unsigned b1)
{
    asm volatile("mma.sync.aligned.m16n8k16.row.col.f32.f16.f16.f32 "
                 "{%0,%1,%2,%3}, {%4,%5,%6,%7}, {%8,%9}, {%0,%1,%2,%3};"
                 : "+f"(c0), "+f"(c1), "+f"(c2), "+f"(c3)
                 : "r"(a0), "r"(a1), "r"(a2), "r"(a3), "r"(b0), "r"(b1));
}

__device__ __forceinline__ void ldmatrix_x4(unsigned& r0, unsigned& r1, unsigned& r2, unsigned& r3,
                                            unsigned saddr)
{
    asm volatile("ldmatrix.sync.aligned.m8n8.x4.shared.b16 {%0,%1,%2,%3}, [%4];"
                 : "=r"(r0), "=r"(r1), "=r"(r2), "=r"(r3) : "r"(saddr));
}

__device__ __forceinline__ unsigned sel4(unsigned v0, unsigned v1, unsigned v2, unsigned v3, int c)
{
    unsigned x = (c & 1) ? v1 : v0;
    unsigned y = (c & 1) ? v3 : v2;
    return (c & 2) ? y : x;
}

__global__ void __launch_bounds__(TPB, 1)
rvq_main_kernel(const float* __restrict__ x,
                const float* __restrict__ codebooks,
                float* __restrict__ out)
{
    extern __shared__ __align__(16) char smraw[];
    __half*  s_hb   = (__half*)(smraw + OFF_HB);     // [1024] rows of -2e, 80B stride
    __half2* s_enh2 = (__half2*)(smraw + OFF_ENH);   // [512] half2 enorm pairs
    float*   s_cb   = (float*)(smraw + OFF_CB);      // [1024][36] fp32 rows, en@32

    unsigned sbase;
    asm("{ .reg .u64 t; cvta.to.shared.u64 t, %1; cvt.u32.u64 %0, t; }"
        : "=r"(sbase) : "l"(smraw));

    const int tid  = threadIdx.x;
    const int lane = tid & 31;
    const int tg   = lane & 3;

    // --- stage: fp32 rows (+exact enorm @32) ; half rows = -2e ; half enorm ---
    for (int c = tid; c < NQ * NK; c += TPB) {
        const float* g  = codebooks + (size_t)c * DIM;
        float*       d  = s_cb + (size_t)c * ROWF;
        __half*      ph = (__half*)((char*)s_hb + (size_t)c * ROWHB);
        float en = 0.f;
        #pragma unroll
        for (int i = 0; i < DIM; i++) {
            float v = g[i];
            d[i]  = v;
            ph[i] = __float2half_rn(-2.0f * v);
            en = __fadd_rn(en, __fmul_rn(v, v));
        }
        d[32] = en;                                   // exact enorm (verify)
        ((__half*)s_enh2)[c] = __float2half_rn(en);   // approx enorm (scan)
    }
    __syncthreads();

    const unsigned b_lanebase = sbase + OFF_HB
        + (unsigned)(lane & 7) * ROWHB + ((unsigned)(lane >> 3) << 4);

    const float INF = __int_as_float(0x7f800000);
    double lsum = 0.0;

    for (int chunk = blockIdx.x; chunk < NCHUNK; chunk += GRID) {
        const int n = chunk * TPB + tid;

        float r[DIM], xq[DIM];
        {
            const float4* xr = (const float4*)(x + (size_t)n * DIM);
            #pragma unroll
            for (int j = 0; j < 8; j++) {
                float4 v = xr[j];
                r[4*j+0] = v.x; r[4*j+1] = v.y; r[4*j+2] = v.z; r[4*j+3] = v.w;
                xq[4*j+0] = 0.f; xq[4*j+1] = 0.f; xq[4*j+2] = 0.f; xq[4*j+3] = 0.f;
            }
        }

        float* oi = out + (size_t)N_PTS * DIM + 1 + (size_t)n * NQ;

        #pragma unroll 1
        for (int q = 0; q < NQ; q++) {
            // exact sequential rnorm (reference rounding)
            float rn = 0.f;
            #pragma unroll
            for (int i = 0; i < DIM; i++)
                rn = __fadd_rn(rn, __fmul_rn(r[i], r[i]));

            // ---- A fragments via shuffles (R6-validated mapping) ----
            unsigned h2u[16];
            #pragma unroll
            for (int w = 0; w < 16; w++) {
                __half2 hh = __floats2half2_rn(r[2*w], r[2*w+1]);
                h2u[w] = *(unsigned*)&hh;
            }
            unsigned A0[8], A1[8];
            #pragma unroll
            for (int mt = 0; mt < 2; mt++) {
                unsigned* A = mt ? A1 : A0;
                int src0 = mt * 16 + (lane >> 2);
                int src1 = src0 + 8;
                #pragma unroll
                for (int b4 = 0; b4 < 4; b4++) {
                    unsigned s00 = __shfl_sync(0xffffffffu, h2u[4*b4+0], src0);
                    unsigned s01 = __shfl_sync(0xffffffffu, h2u[4*b4+1], src0);
                    unsigned s02 = __shfl_sync(0xffffffffu, h2u[4*b4+2], src0);
                    unsigned s03 = __shfl_sync(0xffffffffu, h2u[4*b4+3], src0);
                    unsigned s10 = __shfl_sync(0xffffffffu, h2u[4*b4+0], src1);
                    unsigned s11 = __shfl_sync(0xffffffffu, h2u[4*b4+1], src1);
                    unsigned s12 = __shfl_sync(0xffffffffu, h2u[4*b4+2], src1);
                    unsigned s13 = __shfl_sync(0xffffffffu, h2u[4*b4+3], src1);
                    A[2*b4 + 0] = sel4(s00, s01, s02, s03, tg);
                    A[2*b4 + 1] = sel4(s10, s11, s12, s13, tg);
                }
            }

            const unsigned bq    = b_lanebase + (unsigned)q * NK * ROWHB;
            const __half2* enq2  = s_enh2 + q * (NK / 2);
            const float*   cq    = s_cb + (size_t)q * NK * ROWF;

            // ---- tensor-core scan: score = en - 2*dot (C-init = en, B = -2e) ----
            unsigned long long f00 = 0, f01 = 0, f10 = 0, f11 = 0;
            float th00 = INF, th01 = INF, th10 = INF, th11 = INF;

            #pragma unroll
            for (int t = 0; t < 32; t++) {
                unsigned b0, b1, b2, b3;
                ldmatrix_x4(b0, b1, b2, b3, bq + (unsigned)t * (8 * ROWHB));
                float2 en2 = __half22float2(enq2[t * 4 + tg]);

                // mt = 0 (points 0-15)
                {
                    float s0 = en2.x, s1 = en2.y, s2 = en2.x, s3 = en2.y;
                    mma16816(s0, s1, s2, s3, A0[0], A0[1], A0[2], A0[3], b0, b1);
                    mma16816(s0, s1, s2, s3, A0[4], A0[5], A0[6], A0[7], b2, b3);
                    th00 = fminf(th00, fminf(s0, s1) + EPS);
                    th01 = fminf(th01, fminf(s2, s3) + EPS);
                    f00 |= (((unsigned long long)(s0 <= th00))
                          | ((unsigned long long)(s1 <= th00) << 1)) << (2*t);
                    f01 |= (((unsigned long long)(s2 <= th01))
                          | ((unsigned long long)(s3 <= th01) << 1)) << (2*t);
                }
                // mt = 1 (points 16-31)
                {
                    float s0 = en2.x, s1 = en2.y, s2 = en2.x, s3 = en2.y;
                    mma16816(s0, s1, s2, s3, A1[0], A1[1], A1[2], A1[3], b0, b1);
                    mma16816(s0, s1, s2, s3, A1[4], A1[5], A1[6], A1[7], b2, b3);
                    th10 = fminf(th10, fminf(s0, s1) + EPS);
                    th11 = fminf(th11, fminf(s2, s3) + EPS);
                    f10 |= (((unsigned long long)(s0 <= th10))
                          | ((unsigned long long)(s1 <= th10) << 1)) << (2*t);
                    f11 |= (((unsigned long long)(s2 <= th11))
                          | ((unsigned long long)(s3 <= th11) << 1)) << (2*t);
                }
                // quad-sync thresholds every 4 tiles (superset-safe tightening)
                if ((t & 3) == 3) {
                    th00 = fminf(th00, __shfl_xor_sync(0xffffffffu, th00, 1));
                    th00 = fminf(th00, __shfl_xor_sync(0xffffffffu, th00, 2));
                    th01 = fminf(th01, __shfl_xor_sync(0xffffffffu, th01, 1));
                    th01 = fminf(th01, __shfl_xor_sync(0xffffffffu, th01, 2));
                    th10 = fminf(th10, __shfl_xor_sync(0xffffffffu, th10, 1));
                    th10 = fminf(th10, __shfl_xor_sync(0xffffffffu, th10, 2));
                    th11 = fminf(th11, __shfl_xor_sync(0xffffffffu, th11, 1));
                    th11 = fminf(th11, __shfl_xor_sync(0xffffffffu, th11, 2));
                }
            }

            // ---- gather flags to owning point (R6-validated) ----
            const int rr      = lane & 15;
            const int mycombo = ((lane >> 4) << 1) | (rr >= 8 ? 1 : 0);
            const int srcbase = (rr & 7) << 2;
            unsigned long long gw[4];
            #pragma unroll
            for (int j = 0; j < 4; j++) {
                int src = srcbase + j;
                unsigned long long t0 = __shfl_sync(0xffffffffu, f00, src);
                unsigned long long t1 = __shfl_sync(0xffffffffu, f01, src);
                unsigned long long t2 = __shfl_sync(0xffffffffu, f10, src);
                unsigned long long t3 = __shfl_sync(0xffffffffu, f11, src);
                gw[j] = (mycombo == 0) ? t0 : (mycombo == 1) ? t1
                      : (mycombo == 2) ? t2 : t3;
            }

            int bi;
            const int ncand = __popcll(gw[0]) + __popcll(gw[1])
                            + __popcll(gw[2]) + __popcll(gw[3]);
            if (ncand == 1) {
                // singleton superset of {exact argmin} => it IS the argmin; skip verify
                int j = gw[0] ? 0 : gw[1] ? 1 : gw[2] ? 2 : 3;
                unsigned long long w = gw[j];
                int b = __ffsll((long long)w) - 1;
                bi = ((b >> 1) << 3) + 2 * j + (b & 1);
            } else {
                // ---- exact verification (reference rounding); tie-break: smaller k ----
                float best = INF;
                bi = 0;
                #pragma unroll
                for (int j = 0; j < 4; j++) {
                    unsigned long long msk = gw[j];
                    while (msk) {
                        int b = __ffsll((long long)msk) - 1;
                        msk &= msk - 1;
                        int k = ((b >> 1) << 3) + 2 * j + (b & 1);
                        const float4* e4 = (const float4*)(cq + (size_t)k * ROWF);
                        float acc = 0.f;
                        #pragma unroll
                        for (int jj = 0; jj < 8; jj++) {
                            float4 v = e4[jj];
                            acc = fmaf(r[4*jj+0], v.x, acc);
                            acc = fmaf(r[4*jj+1], v.y, acc);
                            acc = fmaf(r[4*jj+2], v.z, acc);
                            acc = fmaf(r[4*jj+3], v.w, acc);
                        }
                        float s = __fadd_rn(rn, -2.0f * acc);
                        s = __fadd_rn(s, cq[(size_t)k * ROWF + 32]);
                        if (s < best || (s == best && k < bi)) { best = s; bi = k; }
                    }
                }
            }

            oi[q] = (float)bi;

            // ---- exact scan-carry: c=fl(q-r); x_res=fl(r+c); xq+=x_res; r-=x_res ----
            const float4* eb4 = (const float4*)(cq + (size_t)bi * ROWF);
            float lq = 0.f;
            #pragma unroll
            for (int jj = 0; jj < 8; jj++) {
                float4 v = eb4[jj];
                float qv[4] = {v.x, v.y, v.z, v.w};
                #pragma unroll
                for (int u = 0; u < 4; u++) {
                    int i = 4*jj + u;
                    float c   = __fadd_rn(qv[u], -r[i]);
                    float xr_ = __fadd_rn(r[i], c);
                    xq[i]     = __fadd_rn(xq[i], xr_);
                    r[i]      = __fadd_rn(r[i], -xr_);
                    lq       += __fmul_rn(c, c);
                }
            }
            lsum += (double)lq;
        }

        // write x_q
        {
            float4* o = (float4*)(out + (size_t)n * DIM);
            #pragma unroll
            for (int j = 0; j < 8; j++) {
                float4 v;
                v.x = xq[4*j+0]; v.y = xq[4*j+1]; v.z = xq[4*j+2]; v.w = xq[4*j+3];
                o[j] = v;
            }
        }
    }

    // ---- deterministic per-CTA loss reduction ----
    #pragma unroll
    for (int o = 16; o > 0; o >>= 1)
        lsum += __shfl_down_sync(0xffffffffu, lsum, o);

    __shared__ double wsum[TPB / 32];
    if ((tid & 31) == 0) wsum[tid >> 5] = lsum;
    __syncthreads();
    if (tid == 0) {
        double s = 0.0;
        #pragma unroll
        for (int w = 0; w < TPB / 32; w++) s += wsum[w];
        g_block_loss[blockIdx.x] = s;
    }

    // ---- fused finalize: last CTA reduces block sums ----
    __threadfence();
    __shared__ int s_last;
    if (tid == 0) {
        unsigned o = atomicAdd(&g_done, 1u);
        s_last = (o == GRID - 1);
    }
    __syncthreads();
    if (s_last) {
        double v = (tid < GRID) ? g_block_loss[tid] : 0.0;
        #pragma unroll
        for (int o = 16; o > 0; o >>= 1)
            v += __shfl_down_sync(0xffffffffu, v, o);
        if ((tid & 31) == 0) wsum[tid >> 5] = v;
        __syncthreads();
        if (tid == 0) {
            double s = 0.0;
            #pragma unroll
            for (int w = 0; w < TPB / 32; w++) s += wsum[w];
            out[(size_t)N_PTS * DIM] =
                (float)(1.25 * s / ((double)NQ * (double)N_PTS * (double)DIM));
            g_done = 0;   // reset for next graph replay
        }
    }
}

extern "C" void kernel_launch(void* const* d_in, const int* in_sizes, int n_in,
                              void* d_out, int out_size)
{
    const float* x   = (const float*)d_in[0];
    const float* cb  = (const float*)d_in[1];
    float*       out = (float*)d_out;

    cudaFuncSetAttribute(rvq_main_kernel,
                         cudaFuncAttributeMaxDynamicSharedMemorySize, SMEM_BYTES);

    rvq_main_kernel<<<GRID, TPB, SMEM_BYTES>>>(x, cb, out);
}